// round 3
// baseline (speedup 1.0000x reference)
#include <cuda_runtime.h>
#include <cstdint>

// LocallyConnected2d: B=16, C=32, H=W=64, K=3, pad=1, stride=1
// out[b, o, l] = sum_i patch[b, l, i] * w[l, i, o] + bias[l, o]
// i = c*9 + ki*3 + kj ; patch samples x[b, c, oh-1+ki, ow-1+kj] (0 OOB)
//
// 1 CTA (128 thr) = 2x2 output tile = 4 warps, 1 warp per location.
// Lane owns 2 output channels (o = 2*lane, 2*lane+1).
// Shared x tile: [c][r(4)][col(4)][b(16)] for the 4x4 input window union.
// Weight stream software-pipelined in registers (wreg[9], refill after use).

#define BATCH   16
#define CIN     32
#define INFEAT  288
#define OC      64
#define TILE_ELEMS (CIN * 4 * 4 * BATCH)   // 8192 floats = 32KB exactly

__global__ __launch_bounds__(128, 7) void lc2d_kernel(
    const float* __restrict__ x,      // (16, 32, 64, 64)
    const float* __restrict__ w,      // (4096, 288, 64)
    const float* __restrict__ bias,   // (4096, 64)
    float* __restrict__ out)          // (16, 64, 64, 64)
{
    __shared__ float tile[TILE_ELEMS];

    const int cta = blockIdx.x;            // 1024 CTAs = 32x32 tiles
    const int th  = cta >> 5;
    const int tw  = cta & 31;
    const int H0  = 2 * th - 1;
    const int W0  = 2 * tw - 1;
    const int tid = threadIdx.x;

    // ---- Stage 4x4 x-window for all channels/batches (L2-resident x) ----
    for (int e = tid; e < TILE_ELEMS; e += 128) {
        int col = e & 3;
        int r   = (e >> 2) & 3;
        int c   = (e >> 4) & 31;
        int b   = e >> 9;
        int h   = H0 + r;
        int ww  = W0 + col;
        float v = 0.0f;
        if ((unsigned)h < 64u && (unsigned)ww < 64u)
            v = __ldg(&x[((((b * CIN + c) << 6) + h) << 6) + ww]);
        tile[((c * 4 + r) * 4 + col) * BATCH + b] = v;
    }
    __syncthreads();

    const int wid  = tid >> 5;
    const int lane = tid & 31;
    const int dy   = wid >> 1;
    const int dx   = wid & 1;
    const int l    = ((2 * th + dy) << 6) + (2 * tw + dx);

    const float* wp = w + (size_t)l * (INFEAT * OC) + 2 * lane;
    uint32_t sbase = (uint32_t)__cvta_generic_to_shared(tile)
                   + (uint32_t)((dy * 64 + dx * 16) * 4);

    // acc0[j] : oc=2*lane,   batches (2j, 2j+1) packed f32x2
    // acc1[j] : oc=2*lane+1, batches (2j, 2j+1) packed f32x2
    unsigned long long acc0[8], acc1[8];
#pragma unroll
    for (int j = 0; j < 8; j++) { acc0[j] = 0ull; acc1[j] = 0ull; }

    // Prime the weight pipeline: 9 (ki,kj) pairs for channel 0
    float2 wreg[9];
#pragma unroll
    for (int k = 0; k < 9; k++)
        wreg[k] = __ldcs((const float2*)(wp + k * OC));

    for (int c = 0; c < CIN; c++) {
#pragma unroll
        for (int k = 0; k < 9; k++) {
            const int ki = k / 3;
            const int kj = k - ki * 3;

            unsigned long long w0, w1;
            asm("mov.b64 %0, {%1, %1};" : "=l"(w0) : "f"(wreg[k].x));
            asm("mov.b64 %0, {%1, %1};" : "=l"(w1) : "f"(wreg[k].y));

            uint32_t a = sbase + (uint32_t)(c * 1024)
                       + (uint32_t)((ki * 64 + kj * 16) * 4);
            unsigned long long p0, p1, p2, p3, p4, p5, p6, p7;
            asm("ld.shared.v2.b64 {%0,%1}, [%2];" : "=l"(p0), "=l"(p1) : "r"(a));
            asm("ld.shared.v2.b64 {%0,%1}, [%2];" : "=l"(p2), "=l"(p3) : "r"(a + 16));
            asm("ld.shared.v2.b64 {%0,%1}, [%2];" : "=l"(p4), "=l"(p5) : "r"(a + 32));
            asm("ld.shared.v2.b64 {%0,%1}, [%2];" : "=l"(p6), "=l"(p7) : "r"(a + 48));

            asm("fma.rn.f32x2 %0, %1, %2, %0;" : "+l"(acc0[0]) : "l"(p0), "l"(w0));
            asm("fma.rn.f32x2 %0, %1, %2, %0;" : "+l"(acc0[1]) : "l"(p1), "l"(w0));
            asm("fma.rn.f32x2 %0, %1, %2, %0;" : "+l"(acc0[2]) : "l"(p2), "l"(w0));
            asm("fma.rn.f32x2 %0, %1, %2, %0;" : "+l"(acc0[3]) : "l"(p3), "l"(w0));
            asm("fma.rn.f32x2 %0, %1, %2, %0;" : "+l"(acc0[4]) : "l"(p4), "l"(w0));
            asm("fma.rn.f32x2 %0, %1, %2, %0;" : "+l"(acc0[5]) : "l"(p5), "l"(w0));
            asm("fma.rn.f32x2 %0, %1, %2, %0;" : "+l"(acc0[6]) : "l"(p6), "l"(w0));
            asm("fma.rn.f32x2 %0, %1, %2, %0;" : "+l"(acc0[7]) : "l"(p7), "l"(w0));

            asm("fma.rn.f32x2 %0, %1, %2, %0;" : "+l"(acc1[0]) : "l"(p0), "l"(w1));
            asm("fma.rn.f32x2 %0, %1, %2, %0;" : "+l"(acc1[1]) : "l"(p1), "l"(w1));
            asm("fma.rn.f32x2 %0, %1, %2, %0;" : "+l"(acc1[2]) : "l"(p2), "l"(w1));
            asm("fma.rn.f32x2 %0, %1, %2, %0;" : "+l"(acc1[3]) : "l"(p3), "l"(w1));
            asm("fma.rn.f32x2 %0, %1, %2, %0;" : "+l"(acc1[4]) : "l"(p4), "l"(w1));
            asm("fma.rn.f32x2 %0, %1, %2, %0;" : "+l"(acc1[5]) : "l"(p5), "l"(w1));
            asm("fma.rn.f32x2 %0, %1, %2, %0;" : "+l"(acc1[6]) : "l"(p6), "l"(w1));
            asm("fma.rn.f32x2 %0, %1, %2, %0;" : "+l"(acc1[7]) : "l"(p7), "l"(w1));

            // Refill this slot with channel c+1's weights (deep in-warp lookahead)
            if (c + 1 < CIN)
                wreg[k] = __ldcs((const float2*)(wp + ((c + 1) * 9 + k) * OC));
        }
    }

    // ---- Epilogue ----
    float2 bv = *(const float2*)(bias + l * OC + 2 * lane);
    const int o0 = 2 * lane;
    float* op = out + (size_t)o0 * 4096 + l;   // + b*64*4096 per batch

#pragma unroll
    for (int j = 0; j < 8; j++) {
        float lo0, hi0, lo1, hi1;
        asm("mov.b64 {%0, %1}, %2;" : "=f"(lo0), "=f"(hi0) : "l"(acc0[j]));
        asm("mov.b64 {%0, %1}, %2;" : "=f"(lo1), "=f"(hi1) : "l"(acc1[j]));
        int b0 = 2 * j, b1 = 2 * j + 1;
        op[(size_t)(b0 * OC) * 4096]          = lo0 + bv.x;
        op[(size_t)(b1 * OC) * 4096]          = hi0 + bv.x;
        op[(size_t)(b0 * OC) * 4096 + 4096]   = lo1 + bv.y;
        op[(size_t)(b1 * OC) * 4096 + 4096]   = hi1 + bv.y;
    }
}

extern "C" void kernel_launch(void* const* d_in, const int* in_sizes, int n_in,
                              void* d_out, int out_size) {
    const float* x    = (const float*)d_in[0];
    const float* wgt  = (const float*)d_in[1];
    const float* bias = (const float*)d_in[2];
    float* out        = (float*)d_out;

    lc2d_kernel<<<1024, 128>>>(x, wgt, bias, out);
}

// round 4
// speedup vs baseline: 1.2856x; 1.2856x over previous
#include <cuda_runtime.h>
#include <cstdint>

// LocallyConnected2d: B=16, C=32, H=W=64, K=3, pad=1, stride=1
// out[b, o, l] = sum_i patch[b, l, i] * w[l, i, o] + bias[l, o]
//
// 1 CTA (128 thr) = 2x2 output tile = 4 warps, 1 warp per location.
// Lane owns 2 output channels (o = 2*lane, 2*lane+1).
// x window staged in TWO channel halves of 16 ch (16KB smem) so that
// 7 CTAs/SM fit (reg-limited) -> grid 1024 <= capacity 1036 -> SINGLE WAVE.

#define BATCH   16
#define CIN     32
#define INFEAT  288
#define OC      64
#define TILE_C  16
#define TILE_ELEMS (TILE_C * 4 * 4 * BATCH)   // 4096 floats = 16KB

__global__ __launch_bounds__(128, 7) void lc2d_kernel(
    const float* __restrict__ x,      // (16, 32, 64, 64)
    const float* __restrict__ w,      // (4096, 288, 64)
    const float* __restrict__ bias,   // (4096, 64)
    float* __restrict__ out)          // (16, 64, 64, 64)
{
    __shared__ float tile[TILE_ELEMS];

    const int cta = blockIdx.x;            // 1024 CTAs = 32x32 tiles
    const int th  = cta >> 5;
    const int tw  = cta & 31;
    const int H0  = 2 * th - 1;
    const int W0  = 2 * tw - 1;
    const int tid = threadIdx.x;

    const int wid  = tid >> 5;
    const int lane = tid & 31;
    const int dy   = wid >> 1;
    const int dx   = wid & 1;
    const int l    = ((2 * th + dy) << 6) + (2 * tw + dx);

    const float* wbase = w + (size_t)l * (INFEAT * OC) + 2 * lane;
    uint32_t sbase = (uint32_t)__cvta_generic_to_shared(tile)
                   + (uint32_t)((dy * 64 + dx * 16) * 4);

    // acc0[j] : oc=2*lane,   batches (2j, 2j+1) packed f32x2
    // acc1[j] : oc=2*lane+1, batches (2j, 2j+1) packed f32x2
    unsigned long long acc0[8], acc1[8];
#pragma unroll
    for (int j = 0; j < 8; j++) { acc0[j] = 0ull; acc1[j] = 0ull; }

    // Prime the weight pipeline: 9 (ki,kj) pairs for channel 0
    float2 wreg[9];
#pragma unroll
    for (int k = 0; k < 9; k++)
        wreg[k] = __ldcs((const float2*)(wbase + k * OC));

    for (int phase = 0; phase < 2; phase++) {
        if (phase) __syncthreads();   // protect prior reads before overwrite

        // ---- Stage 16 channels of the 4x4 x-window ----
        for (int e = tid; e < TILE_ELEMS; e += 128) {
            int col = e & 3;
            int r   = (e >> 2) & 3;
            int cc  = (e >> 4) & 15;
            int b   = e >> 8;
            int c   = phase * TILE_C + cc;
            int h   = H0 + r;
            int ww  = W0 + col;
            float v = 0.0f;
            if ((unsigned)h < 64u && (unsigned)ww < 64u)
                v = __ldg(&x[((((b * CIN + c) << 6) + h) << 6) + ww]);
            tile[((cc * 4 + r) * 4 + col) * BATCH + b] = v;
        }
        __syncthreads();

        // ---- Compute 16 channels ----
        for (int cc = 0; cc < TILE_C; cc++) {
            const int c = phase * TILE_C + cc;
#pragma unroll
            for (int k = 0; k < 9; k++) {
                const int ki = k / 3;
                const int kj = k - ki * 3;

                unsigned long long w0, w1;
                asm("mov.b64 %0, {%1, %1};" : "=l"(w0) : "f"(wreg[k].x));
                asm("mov.b64 %0, {%1, %1};" : "=l"(w1) : "f"(wreg[k].y));

                uint32_t a = sbase + (uint32_t)(cc * 1024)
                           + (uint32_t)((ki * 64 + kj * 16) * 4);
                unsigned long long p0, p1, p2, p3, p4, p5, p6, p7;
                asm("ld.shared.v2.b64 {%0,%1}, [%2];" : "=l"(p0), "=l"(p1) : "r"(a));
                asm("ld.shared.v2.b64 {%0,%1}, [%2];" : "=l"(p2), "=l"(p3) : "r"(a + 16));
                asm("ld.shared.v2.b64 {%0,%1}, [%2];" : "=l"(p4), "=l"(p5) : "r"(a + 32));
                asm("ld.shared.v2.b64 {%0,%1}, [%2];" : "=l"(p6), "=l"(p7) : "r"(a + 48));

                asm("fma.rn.f32x2 %0, %1, %2, %0;" : "+l"(acc0[0]) : "l"(p0), "l"(w0));
                asm("fma.rn.f32x2 %0, %1, %2, %0;" : "+l"(acc0[1]) : "l"(p1), "l"(w0));
                asm("fma.rn.f32x2 %0, %1, %2, %0;" : "+l"(acc0[2]) : "l"(p2), "l"(w0));
                asm("fma.rn.f32x2 %0, %1, %2, %0;" : "+l"(acc0[3]) : "l"(p3), "l"(w0));
                asm("fma.rn.f32x2 %0, %1, %2, %0;" : "+l"(acc0[4]) : "l"(p4), "l"(w0));
                asm("fma.rn.f32x2 %0, %1, %2, %0;" : "+l"(acc0[5]) : "l"(p5), "l"(w0));
                asm("fma.rn.f32x2 %0, %1, %2, %0;" : "+l"(acc0[6]) : "l"(p6), "l"(w0));
                asm("fma.rn.f32x2 %0, %1, %2, %0;" : "+l"(acc0[7]) : "l"(p7), "l"(w0));

                asm("fma.rn.f32x2 %0, %1, %2, %0;" : "+l"(acc1[0]) : "l"(p0), "l"(w1));
                asm("fma.rn.f32x2 %0, %1, %2, %0;" : "+l"(acc1[1]) : "l"(p1), "l"(w1));
                asm("fma.rn.f32x2 %0, %1, %2, %0;" : "+l"(acc1[2]) : "l"(p2), "l"(w1));
                asm("fma.rn.f32x2 %0, %1, %2, %0;" : "+l"(acc1[3]) : "l"(p3), "l"(w1));
                asm("fma.rn.f32x2 %0, %1, %2, %0;" : "+l"(acc1[4]) : "l"(p4), "l"(w1));
                asm("fma.rn.f32x2 %0, %1, %2, %0;" : "+l"(acc1[5]) : "l"(p5), "l"(w1));
                asm("fma.rn.f32x2 %0, %1, %2, %0;" : "+l"(acc1[6]) : "l"(p6), "l"(w1));
                asm("fma.rn.f32x2 %0, %1, %2, %0;" : "+l"(acc1[7]) : "l"(p7), "l"(w1));

                // Refill this slot with channel c+1's weights
                if (c + 1 < CIN)
                    wreg[k] = __ldcs((const float2*)(wbase + ((c + 1) * 9 + k) * OC));
            }
        }
    }

    // ---- Epilogue ----
    float2 bv = *(const float2*)(bias + l * OC + 2 * lane);
    const int o0 = 2 * lane;
    float* op = out + (size_t)o0 * 4096 + l;   // + b*64*4096 per batch

#pragma unroll
    for (int j = 0; j < 8; j++) {
        float lo0, hi0, lo1, hi1;
        asm("mov.b64 {%0, %1}, %2;" : "=f"(lo0), "=f"(hi0) : "l"(acc0[j]));
        asm("mov.b64 {%0, %1}, %2;" : "=f"(lo1), "=f"(hi1) : "l"(acc1[j]));
        int b0 = 2 * j, b1 = 2 * j + 1;
        op[(size_t)(b0 * OC) * 4096]          = lo0 + bv.x;
        op[(size_t)(b1 * OC) * 4096]          = hi0 + bv.x;
        op[(size_t)(b0 * OC) * 4096 + 4096]   = lo1 + bv.y;
        op[(size_t)(b1 * OC) * 4096 + 4096]   = hi1 + bv.y;
    }
}

extern "C" void kernel_launch(void* const* d_in, const int* in_sizes, int n_in,
                              void* d_out, int out_size) {
    const float* x    = (const float*)d_in[0];
    const float* wgt  = (const float*)d_in[1];
    const float* bias = (const float*)d_in[2];
    float* out        = (float*)d_out;

    lc2d_kernel<<<1024, 128>>>(x, wgt, bias, out);
}

// round 5
// speedup vs baseline: 1.5117x; 1.1758x over previous
#include <cuda_runtime.h>
#include <cstdint>

// LocallyConnected2d: B=16, C=32, H=W=64, K=3, pad=1, stride=1
// out[b, o, l] = sum_i patch[b, l, i] * w[l, i, o] + bias[l, o]
//
// CTA = 64 threads = 2 warps = 2x2 output locations.
// Warp = 2 locations (one per half-warp, dx = lane>>4). Lane owns 4 output
// channels (oc0 = 4*(lane&15)) for all 16 batches of its half's location.
// Patch LDS.128 broadcasts within each half-warp -> serves 2 locations per instr.
// Weights: one LDG.128 per (c,k) per lane, coalesced, streamed (__ldcs),
// software-pipelined in wreg[9] (refill slot k with channel c+1 after use).
// x window staged in two 16-channel phases (16KB smem) -> 7 CTAs/SM, 1 wave.

#define BATCH   16
#define CIN     32
#define OC      64
#define TILE_C  16
#define TILE_ELEMS (TILE_C * 4 * 4 * BATCH)   // 4096 floats = 16KB

__global__ __launch_bounds__(64, 7) void lc2d_kernel(
    const float* __restrict__ x,      // (16, 32, 64, 64)
    const float* __restrict__ w,      // (4096, 288, 64)
    const float* __restrict__ bias,   // (4096, 64)
    float* __restrict__ out)          // (16, 64, 64, 64)
{
    __shared__ float tile[TILE_ELEMS];   // [cc][r(4)][col(4)][b(16)]

    const int cta = blockIdx.x;            // 1024 CTAs = 32x32 tiles of 2x2
    const int th  = cta >> 5;
    const int tw  = cta & 31;
    const int H0  = 2 * th - 1;
    const int W0  = 2 * tw - 1;
    const int tid = threadIdx.x;

    const int wid    = tid >> 5;       // warp = row of the 2x2 tile (dy)
    const int lane   = tid & 31;
    const int dy     = wid;
    const int dx     = lane >> 4;      // half-warp = column of the 2x2 tile
    const int lane16 = lane & 15;
    const int oc0    = 4 * lane16;
    const int l      = ((2 * th + dy) << 6) + (2 * tw + dx);

    const float* wbase = w + (size_t)l * (288 * OC) + oc0;
    uint32_t sbase = (uint32_t)__cvta_generic_to_shared(tile)
                   + (uint32_t)(dy * 256 + dx * 64);

    // acc[o][j]: oc=oc0+o, batches (2j,2j+1) packed f32x2  -> 32 ull = 64 regs
    unsigned long long acc[4][8];
#pragma unroll
    for (int o = 0; o < 4; o++)
#pragma unroll
        for (int j = 0; j < 8; j++) acc[o][j] = 0ull;

    // Prime weight pipeline: 9 (ki,kj) float4 for channel 0
    float4 wreg[9];
#pragma unroll
    for (int k = 0; k < 9; k++)
        wreg[k] = __ldcs((const float4*)(wbase + k * OC));

    for (int phase = 0; phase < 2; phase++) {
        if (phase) __syncthreads();   // protect prior reads before overwrite

        // ---- Stage 16 channels of the 4x4 x-window ----
        // b fastest -> conflict-free STS (warp writes 128B contiguous)
#pragma unroll 8
        for (int e = tid; e < TILE_ELEMS; e += 64) {
            int b   = e & 15;
            int col = (e >> 4) & 3;
            int r   = (e >> 6) & 3;
            int cc  = e >> 8;
            int c   = phase * TILE_C + cc;
            int h   = H0 + r;
            int ww  = W0 + col;
            float v = 0.0f;
            if ((unsigned)h < 64u && (unsigned)ww < 64u)
                v = __ldg(&x[((((b * CIN + c) << 6) + h) << 6) + ww]);
            tile[((cc * 4 + r) * 4 + col) * BATCH + b] = v;
        }
        __syncthreads();

        // ---- Compute 16 channels ----
        for (int cc = 0; cc < TILE_C; cc++) {
            const int c = phase * TILE_C + cc;
#pragma unroll
            for (int k = 0; k < 9; k++) {
                const int ki = k / 3;
                const int kj = k - ki * 3;

                unsigned long long w2[4];
                asm("mov.b64 %0, {%1, %1};" : "=l"(w2[0]) : "f"(wreg[k].x));
                asm("mov.b64 %0, {%1, %1};" : "=l"(w2[1]) : "f"(wreg[k].y));
                asm("mov.b64 %0, {%1, %1};" : "=l"(w2[2]) : "f"(wreg[k].z));
                asm("mov.b64 %0, {%1, %1};" : "=l"(w2[3]) : "f"(wreg[k].w));

                uint32_t a = sbase + (uint32_t)(cc * 1024 + ki * 256 + kj * 64);
                unsigned long long p0, p1, p2, p3, p4, p5, p6, p7;
                asm("ld.shared.v2.b64 {%0,%1}, [%2];" : "=l"(p0), "=l"(p1) : "r"(a));
                asm("ld.shared.v2.b64 {%0,%1}, [%2];" : "=l"(p2), "=l"(p3) : "r"(a + 16));
                asm("ld.shared.v2.b64 {%0,%1}, [%2];" : "=l"(p4), "=l"(p5) : "r"(a + 32));
                asm("ld.shared.v2.b64 {%0,%1}, [%2];" : "=l"(p6), "=l"(p7) : "r"(a + 48));

#pragma unroll
                for (int o = 0; o < 4; o++) {
                    asm("fma.rn.f32x2 %0, %1, %2, %0;" : "+l"(acc[o][0]) : "l"(p0), "l"(w2[o]));
                    asm("fma.rn.f32x2 %0, %1, %2, %0;" : "+l"(acc[o][1]) : "l"(p1), "l"(w2[o]));
                    asm("fma.rn.f32x2 %0, %1, %2, %0;" : "+l"(acc[o][2]) : "l"(p2), "l"(w2[o]));
                    asm("fma.rn.f32x2 %0, %1, %2, %0;" : "+l"(acc[o][3]) : "l"(p3), "l"(w2[o]));
                    asm("fma.rn.f32x2 %0, %1, %2, %0;" : "+l"(acc[o][4]) : "l"(p4), "l"(w2[o]));
                    asm("fma.rn.f32x2 %0, %1, %2, %0;" : "+l"(acc[o][5]) : "l"(p5), "l"(w2[o]));
                    asm("fma.rn.f32x2 %0, %1, %2, %0;" : "+l"(acc[o][6]) : "l"(p6), "l"(w2[o]));
                    asm("fma.rn.f32x2 %0, %1, %2, %0;" : "+l"(acc[o][7]) : "l"(p7), "l"(w2[o]));
                }

                // Refill slot k with channel c+1 (deep in-warp lookahead)
                if (c + 1 < CIN)
                    wreg[k] = __ldcs((const float4*)(wbase + ((c + 1) * 9 + k) * OC));
            }
        }
    }

    // ---- Epilogue: bias + scatter stores ----
    float4 bv = *(const float4*)(bias + l * OC + oc0);
    const float bvs[4] = {bv.x, bv.y, bv.z, bv.w};
    float* op = out + (size_t)oc0 * 4096 + l;   // + o*4096 + b*64*4096

#pragma unroll
    for (int o = 0; o < 4; o++) {
        float* opo = op + (size_t)o * 4096;
#pragma unroll
        for (int j = 0; j < 8; j++) {
            float lo, hi;
            asm("mov.b64 {%0, %1}, %2;" : "=f"(lo), "=f"(hi) : "l"(acc[o][j]));
            opo[(size_t)(2 * j) * (OC * 4096)]     = lo + bvs[o];
            opo[(size_t)(2 * j + 1) * (OC * 4096)] = hi + bvs[o];
        }
    }
}

extern "C" void kernel_launch(void* const* d_in, const int* in_sizes, int n_in,
                              void* d_out, int out_size) {
    const float* x    = (const float*)d_in[0];
    const float* wgt  = (const float*)d_in[1];
    const float* bias = (const float*)d_in[2];
    float* out        = (float*)d_out;

    lc2d_kernel<<<1024, 64>>>(x, wgt, bias, out);
}